// round 6
// baseline (speedup 1.0000x reference)
#include <cuda_runtime.h>

#define BB 8192
#define TT 256
#define FF 16
#define HH 8
#define FUT 8

typedef unsigned long long u64;

__device__ __forceinline__ float tanhm(float x) {
    float y;
    asm("tanh.approx.f32 %0, %1;" : "=f"(y) : "f"(x));
    return y;
}
__device__ __forceinline__ float sigm(float x) {
    return fmaf(0.5f, tanhm(0.5f * x), 0.5f);
}
__device__ __forceinline__ u64 ffma2(u64 a, u64 b, u64 c) {
    u64 d;
    asm("fma.rn.f32x2 %0, %1, %2, %3;" : "=l"(d) : "l"(a), "l"(b), "l"(c));
    return d;
}
__device__ __forceinline__ u64 pack2(float lo, float hi) {
    u64 r;
    asm("mov.b64 %0, {%1, %2};" : "=l"(r) : "f"(lo), "f"(hi));
    return r;
}
__device__ __forceinline__ float hsum2(u64 v) {
    float lo, hi;
    asm("mov.b64 {%0, %1}, %2;" : "=f"(lo), "=f"(hi) : "l"(v));
    return lo + hi;
}
__device__ __forceinline__ float2 unpack2(u64 v) {
    float lo, hi;
    asm("mov.b64 {%0, %1}, %2;" : "=f"(lo), "=f"(hi) : "l"(v));
    return make_float2(lo, hi);
}

// Weight smem layout (k-pair packed, per [k2][u]):
//   sXif[k2*8+u] = ulonglong2{ (w_i[2k2],w_i[2k2+1]), (w_f[2k2],w_f[2k2+1]) }
//   sXgo[k2*8+u] = same for gates g,o

__global__ __launch_bounds__(64) void LSTM_91122026152229_kernel(
    const float* __restrict__ past,   // [B,T,F]
    const float* __restrict__ fut,    // [B,FUT]
    const float* __restrict__ W1, const float* __restrict__ U1, const float* __restrict__ b1,
    const float* __restrict__ W2, const float* __restrict__ U2, const float* __restrict__ b2,
    const float* __restrict__ Wd1, const float* __restrict__ bd1,
    const float* __restrict__ Wd2, const float* __restrict__ bd2,
    const float* __restrict__ Wo, const float* __restrict__ bo,
    float* __restrict__ out)          // [B,4]
{
    __shared__ ulonglong2 sW1if[8 * 8], sW1go[8 * 8];   // k2 = 0..7
    __shared__ ulonglong2 sU1if[4 * 8], sU1go[4 * 8];   // k2 = 0..3
    __shared__ ulonglong2 sW2if[4 * 8], sW2go[4 * 8];
    __shared__ ulonglong2 sU2if[4 * 8], sU2go[4 * 8];

    const int tid = threadIdx.x;

    // repack W1 (512 floats): src i = f*32 + g*8 + u
    for (int i = tid; i < 512; i += 64) {
        int f = i >> 5, r = i & 31, gg = r >> 3, uu = r & 7;
        int k2 = f >> 1, odd = f & 1;
        float v = W1[i];
        if (gg < 2)
            ((float*)sW1if)[((k2 * 8 + uu) << 2) + gg * 2 + odd] = v;
        else
            ((float*)sW1go)[((k2 * 8 + uu) << 2) + (gg - 2) * 2 + odd] = v;
    }
    // repack U1, W2, U2 (256 floats each)
    for (int i = tid; i < 256; i += 64) {
        int k = i >> 5, r = i & 31, gg = r >> 3, uu = r & 7;
        int k2 = k >> 1, odd = k & 1;
        int fo = ((k2 * 8 + uu) << 2) + ((gg & 1) * 2) + odd;
        float vU1 = U1[i], vW2 = W2[i], vU2 = U2[i];
        if (gg < 2) {
            ((float*)sU1if)[fo] = vU1;
            ((float*)sW2if)[fo] = vW2;
            ((float*)sU2if)[fo] = vU2;
        } else {
            ((float*)sU1go)[fo] = vU1;
            ((float*)sW2go)[fo] = vW2;
            ((float*)sU2go)[fo] = vU2;
        }
    }
    __syncthreads();

    // Each thread: unit u for TWO batch elements eA, eB.
    const int g      = blockIdx.x * 64 + tid;
    const int group8 = g >> 3;
    const int u      = g & 7;
    const int lane   = tid & 31;
    const int base8  = lane & 24;

    const int eA = group8 * 2;
    const int eB = eA + 1;

    const ulonglong2* __restrict__ xpA = (const ulonglong2*)(past + (size_t)eA * (TT * FF));
    const ulonglong2* __restrict__ xpB = (const ulonglong2*)(past + (size_t)eB * (TT * FF));

    // pre-packed biases (accumulator seeds): lo half carries bias, hi half 0
    const u64 Bi1 = pack2(b1[u], 0.f), Bf1 = pack2(b1[u + 8], 0.f);
    const u64 Bg1 = pack2(b1[u + 16], 0.f), Bo1 = pack2(b1[u + 24], 0.f);
    const u64 Bi2 = pack2(b2[u], 0.f), Bf2 = pack2(b2[u + 8], 0.f);
    const u64 Bg2 = pack2(b2[u + 16], 0.f), Bo2 = pack2(b2[u + 24], 0.f);

    float h1A = 0.f, c1A = 0.f, h2A = 0.f, c2A = 0.f;
    float h1B = 0.f, c1B = 0.f, h2B = 0.f, c2B = 0.f;
    u64 hp1A[4], hp1B[4], hp2A[4], hp2B[4];
    #pragma unroll
    for (int j = 0; j < 4; j++) { hp1A[j] = 0ULL; hp1B[j] = 0ULL; hp2A[j] = 0ULL; hp2B[j] = 0ULL; }

    // prefetch x(0): 4 x 16B per element = 8 u64 pairs each
    ulonglong2 a0 = xpA[0], a1 = xpA[1], a2 = xpA[2], a3 = xpA[3];
    ulonglong2 b0v = xpB[0], b1v = xpB[1], b2v = xpB[2], b3v = xpB[3];

    #pragma unroll 1
    for (int t = 0; t < TT; t++) {
        const int tn = (t < TT - 1) ? (t + 1) : t;
        const ulonglong2 nA0 = xpA[tn * 4 + 0];
        const ulonglong2 nA1 = xpA[tn * 4 + 1];
        const ulonglong2 nA2 = xpA[tn * 4 + 2];
        const ulonglong2 nA3 = xpA[tn * 4 + 3];
        const ulonglong2 nB0 = xpB[tn * 4 + 0];
        const ulonglong2 nB1 = xpB[tn * 4 + 1];
        const ulonglong2 nB2 = xpB[tn * 4 + 2];
        const ulonglong2 nB3 = xpB[tn * 4 + 3];

        const u64 xqA[8] = { a0.x, a0.y, a1.x, a1.y, a2.x, a2.y, a3.x, a3.y };
        const u64 xqB[8] = { b0v.x, b0v.y, b1v.x, b1v.y, b2v.x, b2v.y, b3v.x, b3v.y };

        // ---- layer 1 ----
        u64 aiA = Bi1, afA = Bf1, agA = Bg1, aoA = Bo1;
        u64 aiB = Bi1, afB = Bf1, agB = Bg1, aoB = Bo1;
        #pragma unroll
        for (int k2 = 0; k2 < 8; k2++) {
            const ulonglong2 wif = sW1if[k2 * 8 + u];
            const ulonglong2 wgo = sW1go[k2 * 8 + u];
            const u64 xA = xqA[k2], xB = xqB[k2];
            aiA = ffma2(xA, wif.x, aiA);  aiB = ffma2(xB, wif.x, aiB);
            afA = ffma2(xA, wif.y, afA);  afB = ffma2(xB, wif.y, afB);
            agA = ffma2(xA, wgo.x, agA);  agB = ffma2(xB, wgo.x, agB);
            aoA = ffma2(xA, wgo.y, aoA);  aoB = ffma2(xB, wgo.y, aoB);
        }
        #pragma unroll
        for (int k2 = 0; k2 < 4; k2++) {
            const ulonglong2 wif = sU1if[k2 * 8 + u];
            const ulonglong2 wgo = sU1go[k2 * 8 + u];
            const u64 hA = hp1A[k2], hB = hp1B[k2];
            aiA = ffma2(hA, wif.x, aiA);  aiB = ffma2(hB, wif.x, aiB);
            afA = ffma2(hA, wif.y, afA);  afB = ffma2(hB, wif.y, afB);
            agA = ffma2(hA, wgo.x, agA);  agB = ffma2(hB, wgo.x, agB);
            aoA = ffma2(hA, wgo.y, aoA);  aoB = ffma2(hB, wgo.y, aoB);
        }
        {
            const float ziA = hsum2(aiA), zfA = hsum2(afA);
            const float zgA = hsum2(agA), zoA = hsum2(aoA);
            c1A = fmaf(sigm(zfA), c1A, sigm(ziA) * tanhm(zgA));
            h1A = sigm(zoA) * tanhm(c1A);
            const float ziB = hsum2(aiB), zfB = hsum2(afB);
            const float zgB = hsum2(agB), zoB = hsum2(aoB);
            c1B = fmaf(sigm(zfB), c1B, sigm(ziB) * tanhm(zgB));
            h1B = sigm(zoB) * tanhm(c1B);
        }
        // broadcast fresh h1 pairs
        #pragma unroll
        for (int k2 = 0; k2 < 4; k2++) {
            const float aA = __shfl_sync(0xffffffffu, h1A, base8 + 2 * k2);
            const float bA = __shfl_sync(0xffffffffu, h1A, base8 + 2 * k2 + 1);
            const float aB = __shfl_sync(0xffffffffu, h1B, base8 + 2 * k2);
            const float bB = __shfl_sync(0xffffffffu, h1B, base8 + 2 * k2 + 1);
            hp1A[k2] = pack2(aA, bA);
            hp1B[k2] = pack2(aB, bB);
        }

        // ---- layer 2 ----
        u64 yiA = Bi2, yfA = Bf2, ygA = Bg2, yoA = Bo2;
        u64 yiB = Bi2, yfB = Bf2, ygB = Bg2, yoB = Bo2;
        #pragma unroll
        for (int k2 = 0; k2 < 4; k2++) {
            const ulonglong2 wif = sW2if[k2 * 8 + u];
            const ulonglong2 wgo = sW2go[k2 * 8 + u];
            const u64 hA = hp1A[k2], hB = hp1B[k2];
            yiA = ffma2(hA, wif.x, yiA);  yiB = ffma2(hB, wif.x, yiB);
            yfA = ffma2(hA, wif.y, yfA);  yfB = ffma2(hB, wif.y, yfB);
            ygA = ffma2(hA, wgo.x, ygA);  ygB = ffma2(hB, wgo.x, ygB);
            yoA = ffma2(hA, wgo.y, yoA);  yoB = ffma2(hB, wgo.y, yoB);
        }
        #pragma unroll
        for (int k2 = 0; k2 < 4; k2++) {
            const ulonglong2 wif = sU2if[k2 * 8 + u];
            const ulonglong2 wgo = sU2go[k2 * 8 + u];
            const u64 hA = hp2A[k2], hB = hp2B[k2];
            yiA = ffma2(hA, wif.x, yiA);  yiB = ffma2(hB, wif.x, yiB);
            yfA = ffma2(hA, wif.y, yfA);  yfB = ffma2(hB, wif.y, yfB);
            ygA = ffma2(hA, wgo.x, ygA);  ygB = ffma2(hB, wgo.x, ygB);
            yoA = ffma2(hA, wgo.y, yoA);  yoB = ffma2(hB, wgo.y, yoB);
        }
        {
            const float ziA = hsum2(yiA), zfA = hsum2(yfA);
            const float zgA = hsum2(ygA), zoA = hsum2(yoA);
            c2A = fmaf(sigm(zfA), c2A, sigm(ziA) * tanhm(zgA));
            h2A = sigm(zoA) * tanhm(c2A);
            const float ziB = hsum2(yiB), zfB = hsum2(yfB);
            const float zgB = hsum2(ygB), zoB = hsum2(yoB);
            c2B = fmaf(sigm(zfB), c2B, sigm(ziB) * tanhm(zgB));
            h2B = sigm(zoB) * tanhm(c2B);
        }
        // broadcast fresh h2 pairs
        #pragma unroll
        for (int k2 = 0; k2 < 4; k2++) {
            const float aA = __shfl_sync(0xffffffffu, h2A, base8 + 2 * k2);
            const float bA = __shfl_sync(0xffffffffu, h2A, base8 + 2 * k2 + 1);
            const float aB = __shfl_sync(0xffffffffu, h2B, base8 + 2 * k2);
            const float bB = __shfl_sync(0xffffffffu, h2B, base8 + 2 * k2 + 1);
            hp2A[k2] = pack2(aA, bA);
            hp2B[k2] = pack2(aB, bB);
        }

        a0 = nA0; a1 = nA1; a2 = nA2; a3 = nA3;
        b0v = nB0; b1v = nB1; b2v = nB2; b3v = nB3;
    }

    // ---- MLP head for both elements ----
    float h2sA[8], h2sB[8];
    #pragma unroll
    for (int k2 = 0; k2 < 4; k2++) {
        const float2 pA = unpack2(hp2A[k2]);
        const float2 pB = unpack2(hp2B[k2]);
        h2sA[2 * k2] = pA.x; h2sA[2 * k2 + 1] = pA.y;
        h2sB[2 * k2] = pB.x; h2sB[2 * k2 + 1] = pB.y;
    }

    float d1A = bd1[u], d1B = d1A;
    #pragma unroll
    for (int k = 0; k < 8; k++) {
        const float wk = Wd1[k * 8 + u];
        d1A = fmaf(h2sA[k], wk, d1A);
        d1B = fmaf(h2sB[k], wk, d1B);
    }
    const float* __restrict__ fpA = fut + (size_t)eA * FUT;
    const float* __restrict__ fpB = fut + (size_t)eB * FUT;
    #pragma unroll
    for (int k = 0; k < 8; k++) {
        const float wk = Wd1[(8 + k) * 8 + u];
        d1A = fmaf(fpA[k], wk, d1A);
        d1B = fmaf(fpB[k], wk, d1B);
    }
    d1A = fmaxf(d1A, 0.f);
    d1B = fmaxf(d1B, 0.f);

    float d2A = bd2[u], d2B = d2A;
    #pragma unroll
    for (int k = 0; k < 8; k++) {
        const float wk = Wd2[k * 8 + u];
        const float d1kA = __shfl_sync(0xffffffffu, d1A, base8 + k);
        const float d1kB = __shfl_sync(0xffffffffu, d1B, base8 + k);
        d2A = fmaf(d1kA, wk, d2A);
        d2B = fmaf(d1kB, wk, d2B);
    }
    d2A = fmaxf(d2A, 0.f);
    d2B = fmaxf(d2B, 0.f);

    float oA = (u < 4) ? bo[u] : 0.f;
    float oB = oA;
    #pragma unroll
    for (int k = 0; k < 8; k++) {
        const float wk = (u < 4) ? Wo[k * 4 + u] : 0.f;
        const float d2kA = __shfl_sync(0xffffffffu, d2A, base8 + k);
        const float d2kB = __shfl_sync(0xffffffffu, d2B, base8 + k);
        oA = fmaf(d2kA, wk, oA);
        oB = fmaf(d2kB, wk, oB);
    }
    if (u < 4) {
        out[(size_t)eA * 4 + u] = oA;
        out[(size_t)eB * 4 + u] = oB;
    }
}

extern "C" void kernel_launch(void* const* d_in, const int* in_sizes, int n_in,
                              void* d_out, int out_size) {
    const float* past = (const float*)d_in[1];
    const float* fut  = (const float*)d_in[2];
    const float* W1   = (const float*)d_in[3];
    const float* U1   = (const float*)d_in[4];
    const float* b1   = (const float*)d_in[5];
    const float* W2   = (const float*)d_in[6];
    const float* U2   = (const float*)d_in[7];
    const float* b2   = (const float*)d_in[8];
    const float* Wd1  = (const float*)d_in[9];
    const float* bd1  = (const float*)d_in[10];
    const float* Wd2  = (const float*)d_in[11];
    const float* bd2  = (const float*)d_in[12];
    const float* Wo   = (const float*)d_in[13];
    const float* bo   = (const float*)d_in[14];

    // 32768 threads: 2 elements per thread, 8 threads per element-pair
    LSTM_91122026152229_kernel<<<(BB * HH / 2) / 64, 64>>>(
        past, fut, W1, U1, b1, W2, U2, b2, Wd1, bd1, Wd2, bd2, Wo, bo,
        (float*)d_out);
}